// round 13
// baseline (speedup 1.0000x reference)
#include <cuda_runtime.h>
#include <cuda_bf16.h>
#include <cstdint>

#define NROWS 262144
#define CIN   256
#define MID   64
#define KOFF  9
#define EPS   1e-5f

// Pre-split bf16 tables for h2 (device globals; no allocs allowed).
__device__ unsigned short g_h2hi[(size_t)NROWS * MID];
__device__ unsigned short g_h2lo[(size_t)NROWS * MID];
__device__ int g_mask_mode;

// Pre-split w2/w3 tiles in exact smem image: 18432 B = [hi 64x144][lo 64x144].
__device__ uint4 g_w2t[9 * 1152];
__device__ uint4 g_w3t[4 * 1152];

__device__ __forceinline__ uint32_t smem_to_u32(const void* p) {
    uint32_t a;
    asm("{ .reg .u64 t; cvta.to.shared.u64 t, %1; cvt.u32.u64 %0, t; }"
        : "=r"(a) : "l"(p));
    return a;
}

#define LDSM4(r, a)                                                            \
    asm volatile("ldmatrix.sync.aligned.m8n8.x4.shared.b16 {%0,%1,%2,%3}, [%4];" \
        : "=r"((r)[0]), "=r"((r)[1]), "=r"((r)[2]), "=r"((r)[3]) : "r"(a))

#define MMA_BF16(d, a, b)                                                      \
    asm volatile("mma.sync.aligned.m16n8k16.row.col.f32.bf16.bf16.f32 "        \
        "{%0,%1,%2,%3}, {%4,%5,%6,%7}, {%8,%9}, {%0,%1,%2,%3};"                \
        : "+f"((d)[0]), "+f"((d)[1]), "+f"((d)[2]), "+f"((d)[3])               \
        : "r"((a)[0]), "r"((a)[1]), "r"((a)[2]), "r"((a)[3]),                  \
          "r"((b)[0]), "r"((b)[1]))

#define CP_ASYNC16(dst, src, sz)                                               \
    asm volatile("cp.async.cg.shared.global [%0], [%1], 16, %2;"               \
                 :: "r"(dst), "l"(src), "r"(sz))
#define CP_COMMIT() asm volatile("cp.async.commit_group;" ::: "memory")
#define CP_WAIT0()  asm volatile("cp.async.wait_group 0;" ::: "memory")

__device__ __forceinline__ void split2(float v0, float v1, uint32_t& hi, uint32_t& lo) {
    __nv_bfloat16 h0 = __float2bfloat16(v0), h1 = __float2bfloat16(v1);
    __nv_bfloat16 l0 = __float2bfloat16(v0 - __bfloat162float(h0));
    __nv_bfloat16 l1 = __float2bfloat16(v1 - __bfloat162float(h1));
    hi = (uint32_t)__bfloat16_as_ushort(h0) | ((uint32_t)__bfloat16_as_ushort(h1) << 16);
    lo = (uint32_t)__bfloat16_as_ushort(l0) | ((uint32_t)__bfloat16_as_ushort(l1) << 16);
}
__device__ __forceinline__ void split1(float v, unsigned short& h, unsigned short& l) {
    __nv_bfloat16 hb = __float2bfloat16(v);
    __nv_bfloat16 lb = __float2bfloat16(v - __bfloat162float(hb));
    h = __bfloat16_as_ushort(hb); l = __bfloat16_as_ushort(lb);
}

__device__ __forceinline__ bool mask_on(const void* p, size_t i, int mode) {
    switch (mode) {
        case 1:  return ((const unsigned char*)p)[i] != 0;
        case 2:  return ((const float*)p)[i] != 0.0f;
        case 3:  return ((const unsigned short*)p)[i] != 0;
        default: return ((const int*)p)[i] != 0;
    }
}

#define ASTRIDE 144

// ---- 32x64 warp tile over one 64-deep K chunk (R9-proven) ----
__device__ __forceinline__ void gemm_chunk32(uint32_t sb, uint32_t ahi, uint32_t alo,
                                             uint32_t bhi, uint32_t blo,
                                             uint32_t aoff, uint32_t boff,
                                             float acc[2][8][4]) {
    #pragma unroll
    for (int ks = 0; ks < 4; ks++) {
        uint32_t ah0[4], al0[4], ah1[4], al1[4];
        LDSM4(ah0, sb + ahi + aoff + ks * 32);
        LDSM4(ah1, sb + ahi + aoff + 16 * ASTRIDE + ks * 32);
        LDSM4(al0, sb + alo + aoff + ks * 32);
        LDSM4(al1, sb + alo + aoff + 16 * ASTRIDE + ks * 32);
        uint32_t bh[16], bl[16];
        #pragma unroll
        for (int p = 0; p < 4; p++) {
            LDSM4(bh + 4 * p, sb + bhi + boff + p * (16 * ASTRIDE) + ks * 32);
            LDSM4(bl + 4 * p, sb + blo + boff + p * (16 * ASTRIDE) + ks * 32);
        }
        #pragma unroll
        for (int nt = 0; nt < 8; nt++) {
            const uint32_t* fh = bh + (nt >> 1) * 4 + (nt & 1) * 2;
            const uint32_t* fl = bl + (nt >> 1) * 4 + (nt & 1) * 2;
            MMA_BF16(acc[0][nt], ah0, fh);
            MMA_BF16(acc[1][nt], ah1, fh);
            MMA_BF16(acc[0][nt], ah0, fl);
            MMA_BF16(acc[1][nt], ah1, fl);
            MMA_BF16(acc[0][nt], al0, fh);
            MMA_BF16(acc[1][nt], al1, fh);
        }
    }
}

// Transpose a [64k x 64n] f32 weight chunk into split-bf16 B tiles (128 thr).
__device__ __forceinline__ void build_B128(char* smem, uint32_t bhi, uint32_t blo,
                                           const float* __restrict__ wsrc,
                                           int ldw, int tid) {
    const int kr = tid >> 1, ns = (tid & 1) * 32;
    const float4* wr = reinterpret_cast<const float4*>(wsrc + (size_t)kr * ldw + ns);
    #pragma unroll
    for (int q = 0; q < 8; q++) {
        float4 v = wr[q];
        float e[4] = {v.x, v.y, v.z, v.w};
        #pragma unroll
        for (int j = 0; j < 4; j++) {
            int n = ns + q * 4 + j;
            unsigned short h, l; split1(e[j], h, l);
            *(unsigned short*)(smem + bhi + n * ASTRIDE + kr * 2) = h;
            *(unsigned short*)(smem + blo + n * ASTRIDE + kr * 2) = l;
        }
    }
}

// Coalesced async copy of one 18432-B prepped tile into smem (96 thr).
__device__ __forceinline__ void copy_tile96(uint32_t dst, const uint4* src, int tid) {
    #pragma unroll
    for (int i = 0; i < 12; i++)
        CP_ASYNC16(dst + (i * 96 + tid) * 16, (const char*)(src + i * 96 + tid), 16);
}

__device__ __forceinline__ uint32_t a_off(int wr0, int lane) {
    int row = wr0 + (lane & 7) + ((lane >> 3) & 1) * 8;
    return row * ASTRIDE + (lane >> 4) * 16;
}
__device__ __forceinline__ uint32_t b_off(int lane) {
    int n = (lane & 7) + (lane >> 4) * 8;
    return n * ASTRIDE + ((lane >> 3) & 1) * 16;
}

// ---------------------------------------------------------------------------
// Kernel A (R10-identical): h2 = relu(bn2( relu(bn1(x)) @ w1 + b1 )).
// BM=128, 128 threads, warp tile 32x64, 3 CTAs/SM. +13 prep blocks, +1 detect.
// ---------------------------------------------------------------------------
#define A_AHI 0
#define A_ALO 18432
#define A_BHI 36864
#define A_BLO 46080
#define A_PAR 55296

__global__ void __launch_bounds__(128, 3)
kA(const float* __restrict__ x,
   const float* __restrict__ g1, const float* __restrict__ be1,
   const float* __restrict__ mu1, const float* __restrict__ va1,
   const float* __restrict__ w1, const float* __restrict__ b1,
   const float* __restrict__ g2, const float* __restrict__ be2,
   const float* __restrict__ mu2, const float* __restrict__ va2,
   const float* __restrict__ w2, const float* __restrict__ w3,
   const unsigned char* __restrict__ msk)
{
    const int tid = threadIdx.x;

    if (blockIdx.x >= NROWS / 128) {
        const int xb = blockIdx.x - NROWS / 128;
        if (xb < 13) {                       // prep one w2/w3 tile to global
            const float* src; int ldw; unsigned char* d8;
            if (xb < 9) { src = w2 + (size_t)xb * 4096; ldw = MID;
                          d8 = (unsigned char*)(g_w2t + xb * 1152); }
            else        { src = w3 + (xb - 9) * 64;     ldw = CIN;
                          d8 = (unsigned char*)(g_w3t + (xb - 9) * 1152); }
            const int kr = tid >> 1, ns = (tid & 1) * 32;
            const float4* wr = reinterpret_cast<const float4*>(src + (size_t)kr * ldw + ns);
            #pragma unroll
            for (int q = 0; q < 8; q++) {
                float4 v = wr[q];
                float e[4] = {v.x, v.y, v.z, v.w};
                #pragma unroll
                for (int j = 0; j < 4; j++) {
                    int n = ns + q * 4 + j;
                    unsigned short h, l; split1(e[j], h, l);
                    *(unsigned short*)(d8 + n * ASTRIDE + kr * 2)        = h;
                    *(unsigned short*)(d8 + 9216 + n * ASTRIDE + kr * 2) = l;
                }
            }
        } else {                             // mask dtype detection
            __shared__ int flags[3];
            if (tid < 3) flags[tid] = 0;
            __syncthreads();
            int f0 = 0, f1 = 0, f2 = 0;
            #pragma unroll
            for (int q = 0; q < 32; q++) {
                int i = tid * 32 + q;
                unsigned char b = msk[i];
                if (b == 0x3F) { f1 = 1; if ((i & 3) == 1) f0 = 1; }
                else if (b != 0 && (i & 3) != 0) f2 = 1;
            }
            if (f0) atomicOr(&flags[0], 1);
            if (f1) atomicOr(&flags[1], 1);
            if (f2) atomicOr(&flags[2], 1);
            __syncthreads();
            if (tid == 0) {
                int mode;
                if (flags[0])      mode = 3;
                else if (flags[1]) mode = 2;
                else if (flags[2]) mode = 1;
                else               mode = 0;
                g_mask_mode = mode;
            }
        }
        return;
    }

    extern __shared__ char smem[];
    const uint32_t sb = smem_to_u32(smem);
    float* s1 = (float*)(smem + A_PAR);
    float* t1 = s1 + 256; float* s2 = t1 + 256; float* u2 = s2 + 64;

    const int lane = tid & 31, wid = tid >> 5;
    #pragma unroll
    for (int c = tid; c < 256; c += 128) {
        float s = g1[c] * rsqrtf(va1[c] + EPS);
        s1[c] = s; t1[c] = be1[c] - mu1[c] * s;
    }
    if (tid < 64) {
        float s = g2[tid] * rsqrtf(va2[tid] + EPS);
        s2[tid] = s;
        u2[tid] = b1[tid] * s + (be2[tid] - mu2[tid] * s);
    }

    const int m0 = blockIdx.x * 128;
    const float4* xr4 = reinterpret_cast<const float4*>(x + (size_t)(m0 + tid) * CIN);
    const uint32_t aoff = a_off(wid * 32, lane), boff = b_off(lane);
    float acc[2][8][4] = {};

    for (int ch = 0; ch < 4; ch++) {
        __syncthreads();
        #pragma unroll
        for (int q = 0; q < 16; q++) {
            float4 v = xr4[ch * 16 + q];
            int cg = ch * 64 + q * 4;
            float a0 = fmaxf(v.x * s1[cg+0] + t1[cg+0], 0.0f);
            float a1 = fmaxf(v.y * s1[cg+1] + t1[cg+1], 0.0f);
            float a2 = fmaxf(v.z * s1[cg+2] + t1[cg+2], 0.0f);
            float a3 = fmaxf(v.w * s1[cg+3] + t1[cg+3], 0.0f);
            uint32_t h01, l01, h23, l23;
            split2(a0, a1, h01, l01); split2(a2, a3, h23, l23);
            int bo = tid * ASTRIDE + q * 8;
            *(uint32_t*)(smem + A_AHI + bo)     = h01;
            *(uint32_t*)(smem + A_AHI + bo + 4) = h23;
            *(uint32_t*)(smem + A_ALO + bo)     = l01;
            *(uint32_t*)(smem + A_ALO + bo + 4) = l23;
        }
        build_B128(smem, A_BHI, A_BLO, w1 + (size_t)(ch * 64) * MID, MID, tid);
        __syncthreads();
        gemm_chunk32(sb, A_AHI, A_ALO, A_BHI, A_BLO, aoff, boff, acc);
    }

    const int r0 = m0 + wid * 32 + (lane >> 2);
    #pragma unroll
    for (int nt = 0; nt < 8; nt++) {
        int c0 = nt * 8 + (lane & 3) * 2;
        #pragma unroll
        for (int rr = 0; rr < 4; rr++) {
            int r = r0 + rr * 8;
            const float* a = acc[rr >> 1][nt] + (rr & 1) * 2;
            float v0 = fmaxf(a[0] * s2[c0]   + u2[c0],   0.0f);
            float v1 = fmaxf(a[1] * s2[c0+1] + u2[c0+1], 0.0f);
            uint32_t h, l; split2(v0, v1, h, l);
            *(uint32_t*)(g_h2hi + (size_t)r * MID + c0) = h;
            *(uint32_t*)(g_h2lo + (size_t)r * MID + c0) = l;
        }
    }
}

// ---------------------------------------------------------------------------
// Fused kBC: R10 structure (single A + single B buffer, copy-wait-gemm order)
// but 96-thread CTAs (3 warps, BM=96) -> 4 CTAs/SM = 4 independent pipelines.
// smem: A 2*13824 + B 18432 + par 3584 = 49664 B. Last CTA has 32 pad rows.
// ---------------------------------------------------------------------------
#define G_AHI 0
#define G_ALO 13824
#define G_B   27648   /* hi, lo at +9216 */
#define G_PAR 46080   /* s3[64] u3[64] s1a[256] t1a[256] b3a[256] */

__global__ void __launch_bounds__(96, 4)
kBC(const float* __restrict__ x,
    const float* __restrict__ g1, const float* __restrict__ be1,
    const float* __restrict__ mu1, const float* __restrict__ va1,
    const float* __restrict__ b2,
    const float* __restrict__ g3, const float* __restrict__ be3,
    const float* __restrict__ mu3, const float* __restrict__ va3,
    const float* __restrict__ b3,
    const int* __restrict__ nbr, const void* __restrict__ maskp,
    float* __restrict__ out)
{
    extern __shared__ char smem[];
    const uint32_t sb = smem_to_u32(smem);
    float* s3  = (float*)(smem + G_PAR);
    float* u3  = s3 + 64;
    float* s1a = u3 + 64;
    float* t1a = s1a + 256;
    float* b3a = t1a + 256;

    const int tid = threadIdx.x, lane = tid & 31, wid = tid >> 5;
    if (tid < 64) {
        float s = g3[tid] * rsqrtf(va3[tid] + EPS);
        s3[tid] = s;
        u3[tid] = b2[tid] * s + (be3[tid] - mu3[tid] * s);
    }
    for (int c = tid; c < 256; c += 96) {
        float s = g1[c] * rsqrtf(va1[c] + EPS);
        s1a[c] = s; t1a[c] = be1[c] - mu1[c] * s; b3a[c] = b3[c];
    }

    const int m0 = blockIdx.x * 96;
    const int mode = g_mask_mode;
    const uint32_t aoff = a_off(wid * 32, lane), boff = b_off(lane);
    const int grow = m0 + tid;                       // this thread's gather row
    const bool valid = grow < NROWS;
    const size_t eb = (size_t)(valid ? grow : (NROWS - 1)) * KOFF;

    float acc[2][8][4] = {};
    int  nidx = nbr[eb];
    bool non  = valid && mask_on(maskp, eb, mode);

    // ---------------- Phase 1: 9 gather chunks (R10 order) ----------------
    for (int k = 0; k < KOFF; k++) {
        __syncthreads();                 // gemm(k-1) done: A + B reusable
        {                                // gather(k): one h2 row per thread
            uint32_t sz = non ? 16u : 0u;
            const char* hp = (const char*)(g_h2hi + (size_t)nidx * MID);
            const char* lp = (const char*)(g_h2lo + (size_t)nidx * MID);
            uint32_t dh = sb + G_AHI + tid * ASTRIDE;
            uint32_t dl = sb + G_ALO + tid * ASTRIDE;
            #pragma unroll
            for (int q = 0; q < 8; q++) {
                CP_ASYNC16(dh + q * 16, hp + q * 16, sz);
                CP_ASYNC16(dl + q * 16, lp + q * 16, sz);
            }
            CP_COMMIT();
        }
        copy_tile96(sb + G_B, g_w2t + k * 1152, tid); CP_COMMIT();
        if (k < KOFF - 1) {
            nidx = nbr[eb + k + 1];
            non  = valid && mask_on(maskp, eb + k + 1, mode);
        }
        CP_WAIT0();
        __syncthreads();
        gemm_chunk32(sb, G_AHI, G_ALO, G_B, G_B + 9216, aoff, boff, acc);
    }

    // ---------------- Transition: h4 = relu(bn3(acc)) -> A buffer ----------------
    __syncthreads();
    {
        const int rl = wid * 32 + (lane >> 2);
        #pragma unroll
        for (int nt = 0; nt < 8; nt++) {
            int c0 = nt * 8 + (lane & 3) * 2;
            #pragma unroll
            for (int rr = 0; rr < 4; rr++) {
                int r = rl + rr * 8;
                const float* a = acc[rr >> 1][nt] + (rr & 1) * 2;
                float v0 = fmaxf(a[0] * s3[c0]   + u3[c0],   0.0f);
                float v1 = fmaxf(a[1] * s3[c0+1] + u3[c0+1], 0.0f);
                uint32_t h, l; split2(v0, v1, h, l);
                int bo = r * ASTRIDE + c0 * 2;
                *(uint32_t*)(smem + G_AHI + bo) = h;
                *(uint32_t*)(smem + G_ALO + bo) = l;
            }
        }
    }

    // ---------------- Phase 2: 4 col slices of 64 (R10 order) ----------------
    const int rbase = m0 + wid * 32 + (lane >> 2);
    for (int s = 0; s < 4; s++) {
        __syncthreads();                 // h4 ready / prev gemm done with B
        copy_tile96(sb + G_B, g_w3t + s * 1152, tid); CP_COMMIT();
        CP_WAIT0();
        __syncthreads();
        float acc2[2][8][4] = {};
        gemm_chunk32(sb, G_AHI, G_ALO, G_B, G_B + 9216, aoff, boff, acc2);

        #pragma unroll
        for (int nt = 0; nt < 8; nt++) {
            int lc = nt * 8 + (lane & 3) * 2;
            int c = s * 64 + lc;
            #pragma unroll
            for (int rr = 0; rr < 4; rr++) {
                int r = rbase + rr * 8;
                if (r < NROWS) {
                    const float* a = acc2[rr >> 1][nt] + (rr & 1) * 2;
                    float2 xv = *reinterpret_cast<const float2*>(x + (size_t)r * CIN + c);
                    float o0 = a[0] + b3a[c]   + fmaxf(xv.x * s1a[c]   + t1a[c],   0.0f);
                    float o1 = a[1] + b3a[c+1] + fmaxf(xv.y * s1a[c+1] + t1a[c+1], 0.0f);
                    *reinterpret_cast<float2*>(out + (size_t)r * CIN + c) = make_float2(o0, o1);
                }
            }
        }
    }
}

// ---------------------------------------------------------------------------
extern "C" void kernel_launch(void* const* d_in, const int* in_sizes, int n_in,
                              void* d_out, int out_size)
{
    const float* x     = (const float*)d_in[0];
    const float* bn1_g = (const float*)d_in[1];
    const float* bn1_b = (const float*)d_in[2];
    const float* bn1_m = (const float*)d_in[3];
    const float* bn1_v = (const float*)d_in[4];
    const float* w1    = (const float*)d_in[5];
    const float* b1    = (const float*)d_in[6];
    const float* bn2_g = (const float*)d_in[7];
    const float* bn2_b = (const float*)d_in[8];
    const float* bn2_m = (const float*)d_in[9];
    const float* bn2_v = (const float*)d_in[10];
    const float* w2    = (const float*)d_in[11];
    const float* b2    = (const float*)d_in[12];
    const float* bn3_g = (const float*)d_in[13];
    const float* bn3_b = (const float*)d_in[14];
    const float* bn3_m = (const float*)d_in[15];
    const float* bn3_v = (const float*)d_in[16];
    const float* w3    = (const float*)d_in[17];
    const float* b3    = (const float*)d_in[18];
    const int*   nbr   = (const int*)d_in[19];
    const void*  msk   = (const void*)d_in[20];
    float* out = (float*)d_out;

    const int SMA  = A_PAR + (256 + 256 + 64 + 64) * 4;
    const int SMBC = G_PAR + (64 + 64 + 256 + 256 + 256) * 4;   // 49664 B
    cudaFuncSetAttribute(kA,  cudaFuncAttributeMaxDynamicSharedMemorySize, SMA);
    cudaFuncSetAttribute(kBC, cudaFuncAttributeMaxDynamicSharedMemorySize, SMBC);

    kA<<<NROWS / 128 + 14, 128, SMA>>>(x, bn1_g, bn1_b, bn1_m, bn1_v, w1, b1,
                                       bn2_g, bn2_b, bn2_m, bn2_v, w2, w3,
                                       (const unsigned char*)msk);
    kBC<<<(NROWS + 95) / 96, 96, SMBC>>>(x, bn1_g, bn1_b, bn1_m, bn1_v,
                                         b2, bn3_g, bn3_b, bn3_m, bn3_v,
                                         b3, nbr, msk, out);
    (void)in_sizes; (void)n_in; (void)out_size;
}

// round 14
// speedup vs baseline: 1.1624x; 1.1624x over previous
#include <cuda_runtime.h>
#include <cuda_bf16.h>
#include <cstdint>

#define NROWS 262144
#define CIN   256
#define MID   64
#define KOFF  9
#define EPS   1e-5f

// Pre-split bf16 tables for h2 (device globals; no allocs allowed).
__device__ unsigned short g_h2hi[(size_t)NROWS * MID];
__device__ unsigned short g_h2lo[(size_t)NROWS * MID];
__device__ int g_mask_mode;

// Pre-split weight tiles in exact smem image: 18432 B = [hi 64x144][lo 64x144].
__device__ uint4 g_w1t[4 * 1152];
__device__ uint4 g_w2t[9 * 1152];
__device__ uint4 g_w3t[4 * 1152];

__device__ __forceinline__ uint32_t smem_to_u32(const void* p) {
    uint32_t a;
    asm("{ .reg .u64 t; cvta.to.shared.u64 t, %1; cvt.u32.u64 %0, t; }"
        : "=r"(a) : "l"(p));
    return a;
}

#define LDSM4(r, a)                                                            \
    asm volatile("ldmatrix.sync.aligned.m8n8.x4.shared.b16 {%0,%1,%2,%3}, [%4];" \
        : "=r"((r)[0]), "=r"((r)[1]), "=r"((r)[2]), "=r"((r)[3]) : "r"(a))

#define MMA_BF16(d, a, b)                                                      \
    asm volatile("mma.sync.aligned.m16n8k16.row.col.f32.bf16.bf16.f32 "        \
        "{%0,%1,%2,%3}, {%4,%5,%6,%7}, {%8,%9}, {%0,%1,%2,%3};"                \
        : "+f"((d)[0]), "+f"((d)[1]), "+f"((d)[2]), "+f"((d)[3])               \
        : "r"((a)[0]), "r"((a)[1]), "r"((a)[2]), "r"((a)[3]),                  \
          "r"((b)[0]), "r"((b)[1]))

#define CP_ASYNC16(dst, src, sz)                                               \
    asm volatile("cp.async.cg.shared.global [%0], [%1], 16, %2;"               \
                 :: "r"(dst), "l"(src), "r"(sz))
#define CP_COMMIT() asm volatile("cp.async.commit_group;" ::: "memory")
#define CP_WAIT0()  asm volatile("cp.async.wait_group 0;" ::: "memory")

// Fast hi/lo bf16 split: 2 values per cvt.rn.bf16x2.f32, residual via shift/and.
// Bit-identical to the F2FP-based version (same rn rounding at every step).
__device__ __forceinline__ void split2(float v0, float v1, uint32_t& hi, uint32_t& lo) {
    uint32_t h;
    asm("cvt.rn.bf16x2.f32 %0, %1, %2;" : "=r"(h) : "f"(v1), "f"(v0));
    float r0 = v0 - __uint_as_float(h << 16);
    float r1 = v1 - __uint_as_float(h & 0xffff0000u);
    asm("cvt.rn.bf16x2.f32 %0, %1, %2;" : "=r"(lo) : "f"(r1), "f"(r0));
    hi = h;
}
__device__ __forceinline__ void split1(float v, unsigned short& h, unsigned short& l) {
    __nv_bfloat16 hb = __float2bfloat16(v);
    __nv_bfloat16 lb = __float2bfloat16(v - __bfloat162float(hb));
    h = __bfloat16_as_ushort(hb); l = __bfloat16_as_ushort(lb);
}

__device__ __forceinline__ bool mask_on(const void* p, size_t i, int mode) {
    switch (mode) {
        case 1:  return ((const unsigned char*)p)[i] != 0;
        case 2:  return ((const float*)p)[i] != 0.0f;
        case 3:  return ((const unsigned short*)p)[i] != 0;
        default: return ((const int*)p)[i] != 0;
    }
}

#define ASTRIDE 144

// ---- 32x64 warp tile over one 64-deep K chunk (R9-proven) ----
__device__ __forceinline__ void gemm_chunk32(uint32_t sb, uint32_t ahi, uint32_t alo,
                                             uint32_t bhi, uint32_t blo,
                                             uint32_t aoff, uint32_t boff,
                                             float acc[2][8][4]) {
    #pragma unroll
    for (int ks = 0; ks < 4; ks++) {
        uint32_t ah0[4], al0[4], ah1[4], al1[4];
        LDSM4(ah0, sb + ahi + aoff + ks * 32);
        LDSM4(ah1, sb + ahi + aoff + 16 * ASTRIDE + ks * 32);
        LDSM4(al0, sb + alo + aoff + ks * 32);
        LDSM4(al1, sb + alo + aoff + 16 * ASTRIDE + ks * 32);
        uint32_t bh[16], bl[16];
        #pragma unroll
        for (int p = 0; p < 4; p++) {
            LDSM4(bh + 4 * p, sb + bhi + boff + p * (16 * ASTRIDE) + ks * 32);
            LDSM4(bl + 4 * p, sb + blo + boff + p * (16 * ASTRIDE) + ks * 32);
        }
        #pragma unroll
        for (int nt = 0; nt < 8; nt++) {
            const uint32_t* fh = bh + (nt >> 1) * 4 + (nt & 1) * 2;
            const uint32_t* fl = bl + (nt >> 1) * 4 + (nt & 1) * 2;
            MMA_BF16(acc[0][nt], ah0, fh);
            MMA_BF16(acc[1][nt], ah1, fh);
            MMA_BF16(acc[0][nt], ah0, fl);
            MMA_BF16(acc[1][nt], ah1, fl);
            MMA_BF16(acc[0][nt], al0, fh);
            MMA_BF16(acc[1][nt], al1, fh);
        }
    }
}

// Coalesced async copy of one 18432-B prepped tile into smem (128 thr).
__device__ __forceinline__ void copy_tile128(uint32_t dst, const uint4* src, int tid) {
    #pragma unroll
    for (int i = 0; i < 9; i++)
        CP_ASYNC16(dst + (i * 128 + tid) * 16, (const char*)(src + i * 128 + tid), 16);
}

__device__ __forceinline__ uint32_t a_off(int wr0, int lane) {
    int row = wr0 + (lane & 7) + ((lane >> 3) & 1) * 8;
    return row * ASTRIDE + (lane >> 4) * 16;
}
__device__ __forceinline__ uint32_t b_off(int lane) {
    int n = (lane & 7) + (lane >> 4) * 8;
    return n * ASTRIDE + ((lane >> 3) & 1) * 16;
}

// ---------------------------------------------------------------------------
// kPrep: split+transpose all 17 weight tiles (w1:4, w2:9, w3:4) + mask detect.
// ---------------------------------------------------------------------------
__global__ void __launch_bounds__(128)
kPrep(const float* __restrict__ w1, const float* __restrict__ w2,
      const float* __restrict__ w3, const unsigned char* __restrict__ msk)
{
    const int bid = blockIdx.x, tid = threadIdx.x;
    if (bid == 17) {                         // mask dtype detection
        __shared__ int flags[3];
        if (tid < 3) flags[tid] = 0;
        __syncthreads();
        int f0 = 0, f1 = 0, f2 = 0;
        #pragma unroll
        for (int q = 0; q < 32; q++) {
            int i = tid * 32 + q;
            unsigned char b = msk[i];
            if (b == 0x3F) { f1 = 1; if ((i & 3) == 1) f0 = 1; }
            else if (b != 0 && (i & 3) != 0) f2 = 1;
        }
        if (f0) atomicOr(&flags[0], 1);
        if (f1) atomicOr(&flags[1], 1);
        if (f2) atomicOr(&flags[2], 1);
        __syncthreads();
        if (tid == 0) {
            int mode;
            if (flags[0])      mode = 3;
            else if (flags[1]) mode = 2;
            else if (flags[2]) mode = 1;
            else               mode = 0;
            g_mask_mode = mode;
        }
        return;
    }
    const float* src; int ldw; unsigned char* d8;
    if (bid < 4)       { src = w1 + (size_t)bid * 64 * MID;    ldw = MID;
                         d8 = (unsigned char*)(g_w1t + bid * 1152); }
    else if (bid < 13) { src = w2 + (size_t)(bid - 4) * 4096;  ldw = MID;
                         d8 = (unsigned char*)(g_w2t + (bid - 4) * 1152); }
    else               { src = w3 + (bid - 13) * 64;           ldw = CIN;
                         d8 = (unsigned char*)(g_w3t + (bid - 13) * 1152); }
    const int kr = tid >> 1, ns = (tid & 1) * 32;
    const float4* wr = reinterpret_cast<const float4*>(src + (size_t)kr * ldw + ns);
    #pragma unroll
    for (int q = 0; q < 8; q++) {
        float4 v = wr[q];
        float e[4] = {v.x, v.y, v.z, v.w};
        #pragma unroll
        for (int j = 0; j < 4; j++) {
            int n = ns + q * 4 + j;
            unsigned short h, l; split1(e[j], h, l);
            *(unsigned short*)(d8 + n * ASTRIDE + kr * 2)        = h;
            *(unsigned short*)(d8 + 9216 + n * ASTRIDE + kr * 2) = l;
        }
    }
}

// ---------------------------------------------------------------------------
// Kernel A: h2 = relu(bn2( relu(bn1(x)) @ w1 + b1 )). BM=128, 128 threads,
// warp tile 32x64, 3 CTAs/SM. B tiles cp.async'd from g_w1t, issued BEFORE
// the A-build ALU (which hides the copy latency), waited after.
// ---------------------------------------------------------------------------
#define A_AHI 0
#define A_ALO 18432
#define A_BHI 36864   /* lo at 46080; copy covers both (contiguous 18432 B) */
#define A_PAR 55296

__global__ void __launch_bounds__(128, 3)
kA(const float* __restrict__ x,
   const float* __restrict__ g1, const float* __restrict__ be1,
   const float* __restrict__ mu1, const float* __restrict__ va1,
   const float* __restrict__ b1,
   const float* __restrict__ g2, const float* __restrict__ be2,
   const float* __restrict__ mu2, const float* __restrict__ va2)
{
    extern __shared__ char smem[];
    const uint32_t sb = smem_to_u32(smem);
    float* s1 = (float*)(smem + A_PAR);
    float* t1 = s1 + 256; float* s2 = t1 + 256; float* u2 = s2 + 64;

    const int tid = threadIdx.x, lane = tid & 31, wid = tid >> 5;
    #pragma unroll
    for (int c = tid; c < 256; c += 128) {
        float s = g1[c] * rsqrtf(va1[c] + EPS);
        s1[c] = s; t1[c] = be1[c] - mu1[c] * s;
    }
    if (tid < 64) {
        float s = g2[tid] * rsqrtf(va2[tid] + EPS);
        s2[tid] = s;
        u2[tid] = b1[tid] * s + (be2[tid] - mu2[tid] * s);
    }

    const int m0 = blockIdx.x * 128;
    const float4* xr4 = reinterpret_cast<const float4*>(x + (size_t)(m0 + tid) * CIN);
    const uint32_t aoff = a_off(wid * 32, lane), boff = b_off(lane);
    float acc[2][8][4] = {};

    for (int ch = 0; ch < 4; ch++) {
        __syncthreads();                 // gemm(ch-1) done: A + B reusable
        copy_tile128(sb + A_BHI, g_w1t + ch * 1152, tid); CP_COMMIT();
        // A tile: one full 64-channel chunk per thread, bn1+relu+split
        #pragma unroll
        for (int q = 0; q < 16; q++) {
            float4 v = xr4[ch * 16 + q];
            int cg = ch * 64 + q * 4;
            float a0 = fmaxf(v.x * s1[cg+0] + t1[cg+0], 0.0f);
            float a1 = fmaxf(v.y * s1[cg+1] + t1[cg+1], 0.0f);
            float a2 = fmaxf(v.z * s1[cg+2] + t1[cg+2], 0.0f);
            float a3 = fmaxf(v.w * s1[cg+3] + t1[cg+3], 0.0f);
            uint32_t h01, l01, h23, l23;
            split2(a0, a1, h01, l01); split2(a2, a3, h23, l23);
            int bo = tid * ASTRIDE + q * 8;
            *(uint32_t*)(smem + A_AHI + bo)     = h01;
            *(uint32_t*)(smem + A_AHI + bo + 4) = h23;
            *(uint32_t*)(smem + A_ALO + bo)     = l01;
            *(uint32_t*)(smem + A_ALO + bo + 4) = l23;
        }
        CP_WAIT0();
        __syncthreads();
        gemm_chunk32(sb, A_AHI, A_ALO, A_BHI, A_BHI + 9216, aoff, boff, acc);
    }

    const int r0 = m0 + wid * 32 + (lane >> 2);
    #pragma unroll
    for (int nt = 0; nt < 8; nt++) {
        int c0 = nt * 8 + (lane & 3) * 2;
        #pragma unroll
        for (int rr = 0; rr < 4; rr++) {
            int r = r0 + rr * 8;
            const float* a = acc[rr >> 1][nt] + (rr & 1) * 2;
            float v0 = fmaxf(a[0] * s2[c0]   + u2[c0],   0.0f);
            float v1 = fmaxf(a[1] * s2[c0+1] + u2[c0+1], 0.0f);
            uint32_t h, l; split2(v0, v1, h, l);
            *(uint32_t*)(g_h2hi + (size_t)r * MID + c0) = h;
            *(uint32_t*)(g_h2lo + (size_t)r * MID + c0) = l;
        }
    }
}

// ---------------------------------------------------------------------------
// Fused kBC (R10-verbatim structure): 128 threads, warp tile 32x64, 3 CTAs/SM.
// Single A + single B buffer; gather + B copy share one wait.
// ---------------------------------------------------------------------------
#define G_AHI 0
#define G_ALO 18432
#define G_B   36864   /* hi, lo at +9216 */
#define G_PAR 55296

__global__ void __launch_bounds__(128, 3)
kBC(const float* __restrict__ x,
    const float* __restrict__ g1, const float* __restrict__ be1,
    const float* __restrict__ mu1, const float* __restrict__ va1,
    const float* __restrict__ b2,
    const float* __restrict__ g3, const float* __restrict__ be3,
    const float* __restrict__ mu3, const float* __restrict__ va3,
    const float* __restrict__ b3,
    const int* __restrict__ nbr, const void* __restrict__ maskp,
    float* __restrict__ out)
{
    extern __shared__ char smem[];
    const uint32_t sb = smem_to_u32(smem);
    float* s3  = (float*)(smem + G_PAR);
    float* u3  = s3 + 64;
    float* s1a = u3 + 64;
    float* t1a = s1a + 256;
    float* b3a = t1a + 256;

    const int tid = threadIdx.x, lane = tid & 31, wid = tid >> 5;
    if (tid < 64) {
        float s = g3[tid] * rsqrtf(va3[tid] + EPS);
        s3[tid] = s;
        u3[tid] = b2[tid] * s + (be3[tid] - mu3[tid] * s);
    }
    #pragma unroll
    for (int c = tid; c < 256; c += 128) {
        float s = g1[c] * rsqrtf(va1[c] + EPS);
        s1a[c] = s; t1a[c] = be1[c] - mu1[c] * s; b3a[c] = b3[c];
    }

    const int m0 = blockIdx.x * 128;
    const int mode = g_mask_mode;
    const uint32_t aoff = a_off(wid * 32, lane), boff = b_off(lane);
    const size_t eb = (size_t)(m0 + tid) * KOFF;

    float acc[2][8][4] = {};
    int  nidx = nbr[eb];
    bool non  = mask_on(maskp, eb, mode);

    // ---------------- Phase 1: 9 gather chunks ----------------
    for (int k = 0; k < KOFF; k++) {
        __syncthreads();                 // gemm(k-1) done: A + B reusable
        {                                // gather(k): one h2 row per thread
            uint32_t sz = non ? 16u : 0u;
            const char* hp = (const char*)(g_h2hi + (size_t)nidx * MID);
            const char* lp = (const char*)(g_h2lo + (size_t)nidx * MID);
            uint32_t dh = sb + G_AHI + tid * ASTRIDE;
            uint32_t dl = sb + G_ALO + tid * ASTRIDE;
            #pragma unroll
            for (int q = 0; q < 8; q++) {
                CP_ASYNC16(dh + q * 16, hp + q * 16, sz);
                CP_ASYNC16(dl + q * 16, lp + q * 16, sz);
            }
            CP_COMMIT();
        }
        copy_tile128(sb + G_B, g_w2t + k * 1152, tid); CP_COMMIT();
        if (k < KOFF - 1) {
            nidx = nbr[eb + k + 1];
            non  = mask_on(maskp, eb + k + 1, mode);
        }
        CP_WAIT0();
        __syncthreads();
        gemm_chunk32(sb, G_AHI, G_ALO, G_B, G_B + 9216, aoff, boff, acc);
    }

    // ---------------- Transition: h4 = relu(bn3(acc)) -> A buffer ----------------
    __syncthreads();
    {
        const int rl = wid * 32 + (lane >> 2);
        #pragma unroll
        for (int nt = 0; nt < 8; nt++) {
            int c0 = nt * 8 + (lane & 3) * 2;
            #pragma unroll
            for (int rr = 0; rr < 4; rr++) {
                int r = rl + rr * 8;
                const float* a = acc[rr >> 1][nt] + (rr & 1) * 2;
                float v0 = fmaxf(a[0] * s3[c0]   + u3[c0],   0.0f);
                float v1 = fmaxf(a[1] * s3[c0+1] + u3[c0+1], 0.0f);
                uint32_t h, l; split2(v0, v1, h, l);
                int bo = r * ASTRIDE + c0 * 2;
                *(uint32_t*)(smem + G_AHI + bo) = h;
                *(uint32_t*)(smem + G_ALO + bo) = l;
            }
        }
    }

    // ---------------- Phase 2: 4 col slices of 64 ----------------
    const int rbase = m0 + wid * 32 + (lane >> 2);
    for (int s = 0; s < 4; s++) {
        __syncthreads();
        copy_tile128(sb + G_B, g_w3t + s * 1152, tid); CP_COMMIT();
        CP_WAIT0();
        __syncthreads();
        float acc2[2][8][4] = {};
        gemm_chunk32(sb, G_AHI, G_ALO, G_B, G_B + 9216, aoff, boff, acc2);

        #pragma unroll
        for (int nt = 0; nt < 8; nt++) {
            int lc = nt * 8 + (lane & 3) * 2;
            int c = s * 64 + lc;
            #pragma unroll
            for (int rr = 0; rr < 4; rr++) {
                int r = rbase + rr * 8;
                const float* a = acc2[rr >> 1][nt] + (rr & 1) * 2;
                float2 xv = *reinterpret_cast<const float2*>(x + (size_t)r * CIN + c);
                float o0 = a[0] + b3a[c]   + fmaxf(xv.x * s1a[c]   + t1a[c],   0.0f);
                float o1 = a[1] + b3a[c+1] + fmaxf(xv.y * s1a[c+1] + t1a[c+1], 0.0f);
                *reinterpret_cast<float2*>(out + (size_t)r * CIN + c) = make_float2(o0, o1);
            }
        }
    }
}

// ---------------------------------------------------------------------------
extern "C" void kernel_launch(void* const* d_in, const int* in_sizes, int n_in,
                              void* d_out, int out_size)
{
    const float* x     = (const float*)d_in[0];
    const float* bn1_g = (const float*)d_in[1];
    const float* bn1_b = (const float*)d_in[2];
    const float* bn1_m = (const float*)d_in[3];
    const float* bn1_v = (const float*)d_in[4];
    const float* w1    = (const float*)d_in[5];
    const float* b1    = (const float*)d_in[6];
    const float* bn2_g = (const float*)d_in[7];
    const float* bn2_b = (const float*)d_in[8];
    const float* bn2_m = (const float*)d_in[9];
    const float* bn2_v = (const float*)d_in[10];
    const float* w2    = (const float*)d_in[11];
    const float* b2    = (const float*)d_in[12];
    const float* bn3_g = (const float*)d_in[13];
    const float* bn3_b = (const float*)d_in[14];
    const float* bn3_m = (const float*)d_in[15];
    const float* bn3_v = (const float*)d_in[16];
    const float* w3    = (const float*)d_in[17];
    const float* b3    = (const float*)d_in[18];
    const int*   nbr   = (const int*)d_in[19];
    const void*  msk   = (const void*)d_in[20];
    float* out = (float*)d_out;

    const int SMA  = A_PAR + (256 + 256 + 64 + 64) * 4;
    const int SMBC = G_PAR + (64 + 64 + 256 + 256 + 256) * 4;
    cudaFuncSetAttribute(kA,  cudaFuncAttributeMaxDynamicSharedMemorySize, SMA);
    cudaFuncSetAttribute(kBC, cudaFuncAttributeMaxDynamicSharedMemorySize, SMBC);

    kPrep<<<18, 128>>>(w1, w2, w3, (const unsigned char*)msk);
    kA<<<NROWS / 128, 128, SMA>>>(x, bn1_g, bn1_b, bn1_m, bn1_v, b1,
                                  bn2_g, bn2_b, bn2_m, bn2_v);
    kBC<<<NROWS / 128, 128, SMBC>>>(x, bn1_g, bn1_b, bn1_m, bn1_v,
                                    b2, bn3_g, bn3_b, bn3_m, bn3_v,
                                    b3, nbr, msk, out);
    (void)in_sizes; (void)n_in; (void)out_size;
}

// round 15
// speedup vs baseline: 1.7594x; 1.5136x over previous
#include <cuda_runtime.h>
#include <cuda_bf16.h>
#include <cuda_fp16.h>
#include <cstdint>

#define NROWS 262144
#define CIN   256
#define MID   64
#define KOFF  9
#define EPS   1e-5f

// fp16 table for h2 (device global; no allocs allowed).
__device__ unsigned short g_h2[(size_t)NROWS * MID];
__device__ int g_mask_mode;

// Pre-split fp16 weight tiles in exact smem image: 9216 B = 64n x 144B.
__device__ uint4 g_w1t[4 * 576];
__device__ uint4 g_w2t[9 * 576];
__device__ uint4 g_w3t[4 * 576];

__device__ __forceinline__ uint32_t smem_to_u32(const void* p) {
    uint32_t a;
    asm("{ .reg .u64 t; cvta.to.shared.u64 t, %1; cvt.u32.u64 %0, t; }"
        : "=r"(a) : "l"(p));
    return a;
}

#define LDSM4(r, a)                                                            \
    asm volatile("ldmatrix.sync.aligned.m8n8.x4.shared.b16 {%0,%1,%2,%3}, [%4];" \
        : "=r"((r)[0]), "=r"((r)[1]), "=r"((r)[2]), "=r"((r)[3]) : "r"(a))

#define MMA_FP16(d, a, b)                                                      \
    asm volatile("mma.sync.aligned.m16n8k16.row.col.f32.f16.f16.f32 "          \
        "{%0,%1,%2,%3}, {%4,%5,%6,%7}, {%8,%9}, {%0,%1,%2,%3};"                \
        : "+f"((d)[0]), "+f"((d)[1]), "+f"((d)[2]), "+f"((d)[3])               \
        : "r"((a)[0]), "r"((a)[1]), "r"((a)[2]), "r"((a)[3]),                  \
          "r"((b)[0]), "r"((b)[1]))

#define CP_ASYNC16(dst, src, sz)                                               \
    asm volatile("cp.async.cg.shared.global [%0], [%1], 16, %2;"               \
                 :: "r"(dst), "l"(src), "r"(sz))
#define CP_COMMIT() asm volatile("cp.async.commit_group;" ::: "memory")
#define CP_WAIT0()  asm volatile("cp.async.wait_group 0;" ::: "memory")

// Pack two fp32 -> one fp16x2 word (v0 in low half).
__device__ __forceinline__ uint32_t pack2h(float v0, float v1) {
    uint32_t r;
    asm("cvt.rn.f16x2.f32 %0, %1, %2;" : "=r"(r) : "f"(v1), "f"(v0));
    return r;
}

__device__ __forceinline__ bool mask_on(const void* p, size_t i, int mode) {
    switch (mode) {
        case 1:  return ((const unsigned char*)p)[i] != 0;
        case 2:  return ((const float*)p)[i] != 0.0f;
        case 3:  return ((const unsigned short*)p)[i] != 0;
        default: return ((const int*)p)[i] != 0;
    }
}

#define ASTRIDE 144

// ---- 32x64 warp tile over one 64-deep K chunk, single fp16 MMA ----
__device__ __forceinline__ void gemm_chunk32(uint32_t sb, uint32_t abase,
                                             uint32_t bbase,
                                             uint32_t aoff, uint32_t boff,
                                             float acc[2][8][4]) {
    #pragma unroll
    for (int ks = 0; ks < 4; ks++) {
        uint32_t ah0[4], ah1[4];
        LDSM4(ah0, sb + abase + aoff + ks * 32);
        LDSM4(ah1, sb + abase + aoff + 16 * ASTRIDE + ks * 32);
        uint32_t bh[16];
        #pragma unroll
        for (int p = 0; p < 4; p++)
            LDSM4(bh + 4 * p, sb + bbase + boff + p * (16 * ASTRIDE) + ks * 32);
        #pragma unroll
        for (int nt = 0; nt < 8; nt++) {
            const uint32_t* fh = bh + (nt >> 1) * 4 + (nt & 1) * 2;
            MMA_FP16(acc[0][nt], ah0, fh);
            MMA_FP16(acc[1][nt], ah1, fh);
        }
    }
}

// Coalesced async copy of one 9216-B prepped tile into smem (128 thr).
__device__ __forceinline__ void copy_tile128(uint32_t dst, const uint4* src, int tid) {
    #pragma unroll
    for (int i = 0; i < 4; i++)
        CP_ASYNC16(dst + (i * 128 + tid) * 16, (const char*)(src + i * 128 + tid), 16);
    if (tid < 64)
        CP_ASYNC16(dst + (512 + tid) * 16, (const char*)(src + 512 + tid), 16);
}

__device__ __forceinline__ uint32_t a_off(int wr0, int lane) {
    int row = wr0 + (lane & 7) + ((lane >> 3) & 1) * 8;
    return row * ASTRIDE + (lane >> 4) * 16;
}
__device__ __forceinline__ uint32_t b_off(int lane) {
    int n = (lane & 7) + (lane >> 4) * 8;
    return n * ASTRIDE + ((lane >> 3) & 1) * 16;
}

// ---------------------------------------------------------------------------
// kPrep: fp16-convert+transpose all 17 weight tiles (w1:4, w2:9, w3:4) + detect.
// ---------------------------------------------------------------------------
__global__ void __launch_bounds__(128)
kPrep(const float* __restrict__ w1, const float* __restrict__ w2,
      const float* __restrict__ w3, const unsigned char* __restrict__ msk)
{
    const int bid = blockIdx.x, tid = threadIdx.x;
    if (bid == 17) {                         // mask dtype detection
        __shared__ int flags[3];
        if (tid < 3) flags[tid] = 0;
        __syncthreads();
        int f0 = 0, f1 = 0, f2 = 0;
        #pragma unroll
        for (int q = 0; q < 32; q++) {
            int i = tid * 32 + q;
            unsigned char b = msk[i];
            if (b == 0x3F) { f1 = 1; if ((i & 3) == 1) f0 = 1; }
            else if (b != 0 && (i & 3) != 0) f2 = 1;
        }
        if (f0) atomicOr(&flags[0], 1);
        if (f1) atomicOr(&flags[1], 1);
        if (f2) atomicOr(&flags[2], 1);
        __syncthreads();
        if (tid == 0) {
            int mode;
            if (flags[0])      mode = 3;
            else if (flags[1]) mode = 2;
            else if (flags[2]) mode = 1;
            else               mode = 0;
            g_mask_mode = mode;
        }
        return;
    }
    const float* src; int ldw; unsigned char* d8;
    if (bid < 4)       { src = w1 + (size_t)bid * 64 * MID;    ldw = MID;
                         d8 = (unsigned char*)(g_w1t + bid * 576); }
    else if (bid < 13) { src = w2 + (size_t)(bid - 4) * 4096;  ldw = MID;
                         d8 = (unsigned char*)(g_w2t + (bid - 4) * 576); }
    else               { src = w3 + (bid - 13) * 64;           ldw = CIN;
                         d8 = (unsigned char*)(g_w3t + (bid - 13) * 576); }
    const int kr = tid >> 1, ns = (tid & 1) * 32;
    const float4* wr = reinterpret_cast<const float4*>(src + (size_t)kr * ldw + ns);
    #pragma unroll
    for (int q = 0; q < 8; q++) {
        float4 v = wr[q];
        float e[4] = {v.x, v.y, v.z, v.w};
        #pragma unroll
        for (int j = 0; j < 4; j++) {
            int n = ns + q * 4 + j;
            *(unsigned short*)(d8 + n * ASTRIDE + kr * 2) =
                __half_as_ushort(__float2half_rn(e[j]));
        }
    }
}

// ---------------------------------------------------------------------------
// Kernel A: h2 = relu(bn2( relu(bn1(x)) @ w1 + b1 )). BM=128, 128 threads,
// warp tile 32x64, fp16 single-MMA, target 4 CTAs/SM.
// ---------------------------------------------------------------------------
#define A_A   0
#define A_B   18432
#define A_PAR 27648

__global__ void __launch_bounds__(128, 4)
kA(const float* __restrict__ x,
   const float* __restrict__ g1, const float* __restrict__ be1,
   const float* __restrict__ mu1, const float* __restrict__ va1,
   const float* __restrict__ b1,
   const float* __restrict__ g2, const float* __restrict__ be2,
   const float* __restrict__ mu2, const float* __restrict__ va2)
{
    extern __shared__ char smem[];
    const uint32_t sb = smem_to_u32(smem);
    float* s1 = (float*)(smem + A_PAR);
    float* t1 = s1 + 256; float* s2 = t1 + 256; float* u2 = s2 + 64;

    const int tid = threadIdx.x, lane = tid & 31, wid = tid >> 5;
    #pragma unroll
    for (int c = tid; c < 256; c += 128) {
        float s = g1[c] * rsqrtf(va1[c] + EPS);
        s1[c] = s; t1[c] = be1[c] - mu1[c] * s;
    }
    if (tid < 64) {
        float s = g2[tid] * rsqrtf(va2[tid] + EPS);
        s2[tid] = s;
        u2[tid] = b1[tid] * s + (be2[tid] - mu2[tid] * s);
    }

    const int m0 = blockIdx.x * 128;
    const float4* xr4 = reinterpret_cast<const float4*>(x + (size_t)(m0 + tid) * CIN);
    const uint32_t aoff = a_off(wid * 32, lane), boff = b_off(lane);
    float acc[2][8][4] = {};

    for (int ch = 0; ch < 4; ch++) {
        __syncthreads();                 // gemm(ch-1) done: A + B reusable
        copy_tile128(sb + A_B, g_w1t + ch * 576, tid); CP_COMMIT();
        // A tile: one full 64-channel chunk per thread, bn1+relu+fp16 pack
        #pragma unroll
        for (int q = 0; q < 16; q++) {
            float4 v = xr4[ch * 16 + q];
            int cg = ch * 64 + q * 4;
            float a0 = fmaxf(v.x * s1[cg+0] + t1[cg+0], 0.0f);
            float a1 = fmaxf(v.y * s1[cg+1] + t1[cg+1], 0.0f);
            float a2 = fmaxf(v.z * s1[cg+2] + t1[cg+2], 0.0f);
            float a3 = fmaxf(v.w * s1[cg+3] + t1[cg+3], 0.0f);
            int bo = tid * ASTRIDE + q * 8;
            *(uint32_t*)(smem + A_A + bo)     = pack2h(a0, a1);
            *(uint32_t*)(smem + A_A + bo + 4) = pack2h(a2, a3);
        }
        CP_WAIT0();
        __syncthreads();
        gemm_chunk32(sb, A_A, A_B, aoff, boff, acc);
    }

    // epilogue: bn2+relu, fp16 pack, store h2
    const int r0 = m0 + wid * 32 + (lane >> 2);
    #pragma unroll
    for (int nt = 0; nt < 8; nt++) {
        int c0 = nt * 8 + (lane & 3) * 2;
        #pragma unroll
        for (int rr = 0; rr < 4; rr++) {
            int r = r0 + rr * 8;
            const float* a = acc[rr >> 1][nt] + (rr & 1) * 2;
            float v0 = fmaxf(a[0] * s2[c0]   + u2[c0],   0.0f);
            float v1 = fmaxf(a[1] * s2[c0+1] + u2[c0+1], 0.0f);
            *(uint32_t*)(g_h2 + (size_t)r * MID + c0) = pack2h(v0, v1);
        }
    }
}

// ---------------------------------------------------------------------------
// Fused kBC (R14 structure, fp16): 128 threads, warp tile 32x64.
// Single A + single B buffer; gather + B copy share one wait. 4 CTAs/SM tgt.
// ---------------------------------------------------------------------------
#define G_A   0
#define G_B   18432
#define G_PAR 27648

__global__ void __launch_bounds__(128, 4)
kBC(const float* __restrict__ x,
    const float* __restrict__ g1, const float* __restrict__ be1,
    const float* __restrict__ mu1, const float* __restrict__ va1,
    const float* __restrict__ b2,
    const float* __restrict__ g3, const float* __restrict__ be3,
    const float* __restrict__ mu3, const float* __restrict__ va3,
    const float* __restrict__ b3,
    const int* __restrict__ nbr, const void* __restrict__ maskp,
    float* __restrict__ out)
{
    extern __shared__ char smem[];
    const uint32_t sb = smem_to_u32(smem);
    float* s3  = (float*)(smem + G_PAR);
    float* u3  = s3 + 64;
    float* s1a = u3 + 64;
    float* t1a = s1a + 256;
    float* b3a = t1a + 256;

    const int tid = threadIdx.x, lane = tid & 31, wid = tid >> 5;
    if (tid < 64) {
        float s = g3[tid] * rsqrtf(va3[tid] + EPS);
        s3[tid] = s;
        u3[tid] = b2[tid] * s + (be3[tid] - mu3[tid] * s);
    }
    #pragma unroll
    for (int c = tid; c < 256; c += 128) {
        float s = g1[c] * rsqrtf(va1[c] + EPS);
        s1a[c] = s; t1a[c] = be1[c] - mu1[c] * s; b3a[c] = b3[c];
    }

    const int m0 = blockIdx.x * 128;
    const int mode = g_mask_mode;
    const uint32_t aoff = a_off(wid * 32, lane), boff = b_off(lane);
    const size_t eb = (size_t)(m0 + tid) * KOFF;

    float acc[2][8][4] = {};
    int  nidx = nbr[eb];
    bool non  = mask_on(maskp, eb, mode);

    // ---------------- Phase 1: 9 gather chunks ----------------
    for (int k = 0; k < KOFF; k++) {
        __syncthreads();                 // gemm(k-1) done: A + B reusable
        {                                // gather(k): one 128-B h2 row / thread
            uint32_t sz = non ? 16u : 0u;
            const char* hp = (const char*)(g_h2 + (size_t)nidx * MID);
            uint32_t dh = sb + G_A + tid * ASTRIDE;
            #pragma unroll
            for (int q = 0; q < 8; q++)
                CP_ASYNC16(dh + q * 16, hp + q * 16, sz);
            CP_COMMIT();
        }
        copy_tile128(sb + G_B, g_w2t + k * 576, tid); CP_COMMIT();
        if (k < KOFF - 1) {
            nidx = nbr[eb + k + 1];
            non  = mask_on(maskp, eb + k + 1, mode);
        }
        CP_WAIT0();
        __syncthreads();
        gemm_chunk32(sb, G_A, G_B, aoff, boff, acc);
    }

    // ---------------- Transition: h4 = relu(bn3(acc)) -> A buffer ----------------
    __syncthreads();
    {
        const int rl = wid * 32 + (lane >> 2);
        #pragma unroll
        for (int nt = 0; nt < 8; nt++) {
            int c0 = nt * 8 + (lane & 3) * 2;
            #pragma unroll
            for (int rr = 0; rr < 4; rr++) {
                int r = rl + rr * 8;
                const float* a = acc[rr >> 1][nt] + (rr & 1) * 2;
                float v0 = fmaxf(a[0] * s3[c0]   + u3[c0],   0.0f);
                float v1 = fmaxf(a[1] * s3[c0+1] + u3[c0+1], 0.0f);
                *(uint32_t*)(smem + G_A + r * ASTRIDE + c0 * 2) = pack2h(v0, v1);
            }
        }
    }

    // ---------------- Phase 2: 4 col slices of 64 ----------------
    const int rbase = m0 + wid * 32 + (lane >> 2);
    for (int s = 0; s < 4; s++) {
        __syncthreads();
        copy_tile128(sb + G_B, g_w3t + s * 576, tid); CP_COMMIT();
        CP_WAIT0();
        __syncthreads();
        float acc2[2][8][4] = {};
        gemm_chunk32(sb, G_A, G_B, aoff, boff, acc2);

        #pragma unroll
        for (int nt = 0; nt < 8; nt++) {
            int lc = nt * 8 + (lane & 3) * 2;
            int c = s * 64 + lc;
            #pragma unroll
            for (int rr = 0; rr < 4; rr++) {
                int r = rbase + rr * 8;
                const float* a = acc2[rr >> 1][nt] + (rr & 1) * 2;
                float2 xv = *reinterpret_cast<const float2*>(x + (size_t)r * CIN + c);
                float o0 = a[0] + b3a[c]   + fmaxf(xv.x * s1a[c]   + t1a[c],   0.0f);
                float o1 = a[1] + b3a[c+1] + fmaxf(xv.y * s1a[c+1] + t1a[c+1], 0.0f);
                *reinterpret_cast<float2*>(out + (size_t)r * CIN + c) = make_float2(o0, o1);
            }
        }
    }
}

// ---------------------------------------------------------------------------
extern "C" void kernel_launch(void* const* d_in, const int* in_sizes, int n_in,
                              void* d_out, int out_size)
{
    const float* x     = (const float*)d_in[0];
    const float* bn1_g = (const float*)d_in[1];
    const float* bn1_b = (const float*)d_in[2];
    const float* bn1_m = (const float*)d_in[3];
    const float* bn1_v = (const float*)d_in[4];
    const float* w1    = (const float*)d_in[5];
    const float* b1    = (const float*)d_in[6];
    const float* bn2_g = (const float*)d_in[7];
    const float* bn2_b = (const float*)d_in[8];
    const float* bn2_m = (const float*)d_in[9];
    const float* bn2_v = (const float*)d_in[10];
    const float* w2    = (const float*)d_in[11];
    const float* b2    = (const float*)d_in[12];
    const float* bn3_g = (const float*)d_in[13];
    const float* bn3_b = (const float*)d_in[14];
    const float* bn3_m = (const float*)d_in[15];
    const float* bn3_v = (const float*)d_in[16];
    const float* w3    = (const float*)d_in[17];
    const float* b3    = (const float*)d_in[18];
    const int*   nbr   = (const int*)d_in[19];
    const void*  msk   = (const void*)d_in[20];
    float* out = (float*)d_out;

    const int SMA  = A_PAR + (256 + 256 + 64 + 64) * 4;           // 30208 B
    const int SMBC = G_PAR + (64 + 64 + 256 + 256 + 256) * 4;     // 31232 B
    cudaFuncSetAttribute(kA,  cudaFuncAttributeMaxDynamicSharedMemorySize, SMA);
    cudaFuncSetAttribute(kBC, cudaFuncAttributeMaxDynamicSharedMemorySize, SMBC);

    kPrep<<<18, 128>>>(w1, w2, w3, (const unsigned char*)msk);
    kA<<<NROWS / 128, 128, SMA>>>(x, bn1_g, bn1_b, bn1_m, bn1_v, b1,
                                  bn2_g, bn2_b, bn2_m, bn2_v);
    kBC<<<NROWS / 128, 128, SMBC>>>(x, bn1_g, bn1_b, bn1_m, bn1_v,
                                    b2, bn3_g, bn3_b, bn3_m, bn3_v,
                                    b3, nbr, msk, out);
    (void)in_sizes; (void)n_in; (void)out_size;
}